// round 16
// baseline (speedup 1.0000x reference)
#include <cuda_runtime.h>
#include <cstdint>

// Merged-pair tables (rebuilt every call; L2-resident).
// H1/H2 layout (COLUMN-major, split-half): float4 index pair*16 + h*8 + s
//   = column s of M, rows 4h..4h+3.  Main: lane j reads cols -> 128B line/group.
__device__ float H0v[65536 * 8];    // (i0,i1) -> vec[8]   (2MB)
__device__ float H1v[65536 * 64];   // (i2,i3) -> mat^T    (16MB)
__device__ float H2v[65536 * 64];   // (i4,i5) -> mat^T    (16MB)
__device__ float H3v[65536 * 8];    // (i6,a)  -> vec[8]   (2MB)

// ---------------- Fused build kernel (3072 blocks x 128) ----------------
__global__ void __launch_bounds__(128)
build_all(const float* __restrict__ G0, const float* __restrict__ G1,
          const float* __restrict__ G2, const float* __restrict__ G3,
          const float* __restrict__ G4, const float* __restrict__ G5,
          const float* __restrict__ G6, const float* __restrict__ G7)
{
    const int bid = blockIdx.x;
    const int tid = threadIdx.x;

    if (bid < 2048) {
        const bool second = (bid >= 1024);
        const float* A  = second ? G4 : G2;
        const float* Bc = second ? G5 : G3;
        float* Hm       = second ? H2v : H1v;
        const int gt   = (second ? bid - 1024 : bid) * 128 + tid;
        const int pair = gt >> 1;
        const int rh   = gt & 1;          // row-half: rows 4rh..4rh+3
        const int i    = pair >> 8;
        const int j    = pair & 255;

        float4 b[16];
#pragma unroll
        for (int t = 0; t < 8; t++) {
            const float4* Br = (const float4*)(Bc + ((t * 256 + j) * 8));
            b[2 * t]     = __ldg(Br);
            b[2 * t + 1] = __ldg(Br + 1);
        }
        float4 av[8];
#pragma unroll
        for (int rr = 0; rr < 4; rr++) {
            const float4* Ar = (const float4*)(A + (((rh * 4 + rr) * 256 + i) * 8));
            av[2 * rr]     = __ldg(Ar);
            av[2 * rr + 1] = __ldg(Ar + 1);
        }
        float a[4][8];
#pragma unroll
        for (int rr = 0; rr < 4; rr++) {
            a[rr][0] = av[2 * rr].x;     a[rr][1] = av[2 * rr].y;
            a[rr][2] = av[2 * rr].z;     a[rr][3] = av[2 * rr].w;
            a[rr][4] = av[2 * rr + 1].x; a[rr][5] = av[2 * rr + 1].y;
            a[rr][6] = av[2 * rr + 1].z; a[rr][7] = av[2 * rr + 1].w;
        }
        float4 uc[8];
#pragma unroll
        for (int s = 0; s < 8; s++) uc[s] = make_float4(0.f, 0.f, 0.f, 0.f);
#pragma unroll
        for (int t = 0; t < 8; t++) {
            const float bb[8] = { b[2 * t].x, b[2 * t].y, b[2 * t].z, b[2 * t].w,
                                  b[2 * t + 1].x, b[2 * t + 1].y, b[2 * t + 1].z, b[2 * t + 1].w };
#pragma unroll
            for (int s = 0; s < 8; s++) {
                uc[s].x = fmaf(a[0][t], bb[s], uc[s].x);
                uc[s].y = fmaf(a[1][t], bb[s], uc[s].y);
                uc[s].z = fmaf(a[2][t], bb[s], uc[s].z);
                uc[s].w = fmaf(a[3][t], bb[s], uc[s].w);
            }
        }
        float4* dst = (float4*)Hm + (size_t)pair * 16 + rh * 8;
#pragma unroll
        for (int s = 0; s < 8; s++) dst[s] = uc[s];
    } else if (bid < 2560) {
        const int pair = (bid - 2048) * 128 + tid;
        const int i = pair >> 8, j = pair & 255;
        float4 b[16];
#pragma unroll
        for (int t = 0; t < 8; t++) {
            const float4* Br = (const float4*)(G1 + (t * 256 + j) * 8);
            b[2 * t]     = __ldg(Br);
            b[2 * t + 1] = __ldg(Br + 1);
        }
        const float4* Ar = (const float4*)(G0 + i * 8);
        float4 a0 = __ldg(Ar), a1 = __ldg(Ar + 1);
        const float a[8] = { a0.x, a0.y, a0.z, a0.w, a1.x, a1.y, a1.z, a1.w };
        float o[8];
#pragma unroll
        for (int s = 0; s < 8; s++) o[s] = 0.f;
#pragma unroll
        for (int t = 0; t < 8; t++) {
            const float w = a[t];
            o[0] = fmaf(w, b[2 * t].x, o[0]);     o[1] = fmaf(w, b[2 * t].y, o[1]);
            o[2] = fmaf(w, b[2 * t].z, o[2]);     o[3] = fmaf(w, b[2 * t].w, o[3]);
            o[4] = fmaf(w, b[2 * t + 1].x, o[4]); o[5] = fmaf(w, b[2 * t + 1].y, o[5]);
            o[6] = fmaf(w, b[2 * t + 1].z, o[6]); o[7] = fmaf(w, b[2 * t + 1].w, o[7]);
        }
        float4* dst = (float4*)(H0v + (size_t)pair * 8);
        dst[0] = make_float4(o[0], o[1], o[2], o[3]);
        dst[1] = make_float4(o[4], o[5], o[6], o[7]);
    } else {
        const int pair = (bid - 2560) * 128 + tid;
        const int i = pair >> 8, j = pair & 255;
        float b[8];
#pragma unroll
        for (int t = 0; t < 8; t++) b[t] = __ldg(G7 + t * 256 + j);
        float4 av[16];
#pragma unroll
        for (int r = 0; r < 8; r++) {
            const float4* Ar = (const float4*)(G6 + (r * 256 + i) * 8);
            av[2 * r]     = __ldg(Ar);
            av[2 * r + 1] = __ldg(Ar + 1);
        }
        float o[8];
#pragma unroll
        for (int r = 0; r < 8; r++) {
            o[r] = av[2 * r].x * b[0] + av[2 * r].y * b[1]
                 + av[2 * r].z * b[2] + av[2 * r].w * b[3]
                 + av[2 * r + 1].x * b[4] + av[2 * r + 1].y * b[5]
                 + av[2 * r + 1].z * b[6] + av[2 * r + 1].w * b[7];
        }
        float4* dst = (float4*)(H3v + (size_t)pair * 8);
        dst[0] = make_float4(o[0], o[1], o[2], o[3]);
        dst[1] = make_float4(o[4], o[5], o[6], o[7]);
    }
}

// One stage: lane j holds col j (lo=rows0-3, hi=rows4-7); v_j spread over group.
__device__ __forceinline__ float colstage(float v, float4 lo, float4 hi, int gb)
{
    const unsigned F = 0xffffffffu;
    float u;
    u = __shfl_sync(F, v, gb + 0) * lo.x;
    u = fmaf(__shfl_sync(F, v, gb + 1), lo.y, u);
    u = fmaf(__shfl_sync(F, v, gb + 2), lo.z, u);
    u = fmaf(__shfl_sync(F, v, gb + 3), lo.w, u);
    u = fmaf(__shfl_sync(F, v, gb + 4), hi.x, u);
    u = fmaf(__shfl_sync(F, v, gb + 5), hi.y, u);
    u = fmaf(__shfl_sync(F, v, gb + 6), hi.z, u);
    u = fmaf(__shfl_sync(F, v, gb + 7), hi.w, u);
    return u;
}

// ---------------- Main: 8 lanes/element, 2 elements/group ----------------
__global__ void __launch_bounds__(512, 2)
tt_main(const int* __restrict__ states, const int* __restrict__ actions,
        float* __restrict__ out, int Btot)
{
    const unsigned F = 0xffffffffu;
    const int tid  = threadIdx.x;
    const int gw   = blockIdx.x * 16 + (tid >> 5);    // global warp: 8 elements
    const int lane = tid & 31;
    const int g    = lane >> 3;
    const int j    = lane & 7;
    const int gb   = g * 8;

    const int e0 = gw * 8 + g * 2;       // first element of this group
    const int e1 = e0 + 1;
    const int c0 = e0 < Btot ? e0 : 0;
    const int c1 = e1 < Btot ? e1 : 0;

    // Lane j: field j (j<7 -> state, j==7 -> action) of each element.
    int f0 = (j < 7) ? __ldg(states + c0 * 7 + j) : __ldg(actions + c0);
    int f1 = (j < 7) ? __ldg(states + c1 * 7 + j) : __ldg(actions + c1);

    // Pair indices (each lane computes all four via group shuffles).
    const int p0 = __shfl_sync(F, f0, gb + 0) * 256 + __shfl_sync(F, f0, gb + 1);
    const int p1 = __shfl_sync(F, f0, gb + 2) * 256 + __shfl_sync(F, f0, gb + 3);
    const int p2 = __shfl_sync(F, f0, gb + 4) * 256 + __shfl_sync(F, f0, gb + 5);
    const int p3 = __shfl_sync(F, f0, gb + 6) * 256 + __shfl_sync(F, f0, gb + 7);
    const int q0 = __shfl_sync(F, f1, gb + 0) * 256 + __shfl_sync(F, f1, gb + 1);
    const int q1 = __shfl_sync(F, f1, gb + 2) * 256 + __shfl_sync(F, f1, gb + 3);
    const int q2 = __shfl_sync(F, f1, gb + 4) * 256 + __shfl_sync(F, f1, gb + 5);
    const int q3 = __shfl_sync(F, f1, gb + 6) * 256 + __shfl_sync(F, f1, gb + 7);

    // Hoist ALL 10 table loads for both elements (MLP=10/thread).
    const float4* P1a = (const float4*)H1v + (size_t)p1 * 16;
    const float4* P2a = (const float4*)H2v + (size_t)p2 * 16;
    const float4* P1b = (const float4*)H1v + (size_t)q1 * 16;
    const float4* P2b = (const float4*)H2v + (size_t)q2 * 16;
    float  va   = __ldg(H0v + (size_t)p0 * 8 + j);
    float4 lo1a = __ldg(P1a + j);
    float4 hi1a = __ldg(P1a + 8 + j);
    float4 lo2a = __ldg(P2a + j);
    float4 hi2a = __ldg(P2a + 8 + j);
    float  h3a  = __ldg(H3v + (size_t)p3 * 8 + j);
    float  vb   = __ldg(H0v + (size_t)q0 * 8 + j);
    float4 lo1b = __ldg(P1b + j);
    float4 hi1b = __ldg(P1b + 8 + j);
    float4 lo2b = __ldg(P2b + j);
    float4 hi2b = __ldg(P2b + 8 + j);
    float  h3b  = __ldg(H3v + (size_t)q3 * 8 + j);

    // Element a
    va = colstage(va, lo1a, hi1a, gb);
    va = colstage(va, lo2a, hi2a, gb);
    float qa = va * h3a;
    qa += __shfl_xor_sync(F, qa, 1);
    qa += __shfl_xor_sync(F, qa, 2);
    qa += __shfl_xor_sync(F, qa, 4);

    // Element b
    vb = colstage(vb, lo1b, hi1b, gb);
    vb = colstage(vb, lo2b, hi2b, gb);
    float qb = vb * h3b;
    qb += __shfl_xor_sync(F, qb, 1);
    qb += __shfl_xor_sync(F, qb, 2);
    qb += __shfl_xor_sync(F, qb, 4);

    // Lane 0 stores e0, lane 1 stores e1 (butterfly leaves sum on all lanes).
    if (j == 0 && e0 < Btot) out[e0] = qa;
    if (j == 1 && e1 < Btot) out[e1] = qb;
}

extern "C" void kernel_launch(void* const* d_in, const int* in_sizes, int n_in,
                              void* d_out, int out_size)
{
    const float* G0 = (const float*)d_in[0];
    const float* G1 = (const float*)d_in[1];
    const float* G2 = (const float*)d_in[2];
    const float* G3 = (const float*)d_in[3];
    const float* G4 = (const float*)d_in[4];
    const float* G5 = (const float*)d_in[5];
    const float* G6 = (const float*)d_in[6];
    const float* G7 = (const float*)d_in[7];
    const int* states  = (const int*)d_in[8];
    const int* actions = (const int*)d_in[9];
    const int B = in_sizes[9];

    build_all<<<3072, 128>>>(G0, G1, G2, G3, G4, G5, G6, G7);

    // 8 elements per warp, 16 warps per block -> 128 elements per block.
    const int grid = (B + 127) / 128;
    tt_main<<<grid, 512>>>(states, actions, (float*)d_out, B);
}

// round 17
// speedup vs baseline: 1.0520x; 1.0520x over previous
#include <cuda_runtime.h>
#include <cstdint>

// Merged-pair tables (rebuilt every call; L2-resident).
// H1/H2 layout (COLUMN-major, split-half): float4 index pair*16 + h*8 + s
//   = column s of M, rows 4h..4h+3.  Main: lane j reads cols -> 128B line/group.
__device__ float H0v[65536 * 8];    // (i0,i1) -> vec[8]   (2MB)
__device__ float H1v[65536 * 64];   // (i2,i3) -> mat^T    (16MB)
__device__ float H2v[65536 * 64];   // (i4,i5) -> mat^T    (16MB)
__device__ float H3v[65536 * 8];    // (i6,a)  -> vec[8]   (2MB)

// ---------------- Fused build kernel (3072 blocks x 128) ----------------
// bid < 2048 : mid tables, smem-tiled 8x8 pair tiles (64 pairs, 2 thr/pair)
// bid < 2560 : H0   (per-thread)
// else       : H3   (per-thread)
__global__ void __launch_bounds__(128)
build_all(const float* __restrict__ G0, const float* __restrict__ G1,
          const float* __restrict__ G2, const float* __restrict__ G3,
          const float* __restrict__ G4, const float* __restrict__ G5,
          const float* __restrict__ G6, const float* __restrict__ G7)
{
    __shared__ float As[8][65];   // t-major: As[il][t*8+r] = A[(r*256+i)*8+t]
    __shared__ float Bs[8][65];   // t-major: Bs[jl][t*8+s] = B[(t*256+j)*8+s]

    const int bid = blockIdx.x;
    const int tid = threadIdx.x;

    if (bid < 2048) {
        const bool second = (bid >= 1024);
        const float* A  = second ? G4 : G2;
        const float* Bc = second ? G5 : G3;
        float* Hm       = second ? H2v : H1v;
        const int tileid = second ? bid - 1024 : bid;
        const int itile = (tileid >> 5) * 8;
        const int jtile = (tileid & 31) * 8;

        // Stage A/B slices for this tile (512 floats each).
#pragma unroll
        for (int k = tid; k < 512; k += 128) {
            const int sl = k >> 6;          // slice-local index 0..7
            const int x  = k & 63;          // t*8 + c
            const int t  = x >> 3;
            const int c  = x & 7;           // r for A, s for B
            As[sl][x] = __ldg(A  + ((c * 256 + itile + sl) * 8 + t));
            Bs[sl][x] = __ldg(Bc + ((t * 256 + jtile + sl) * 8 + c));
        }
        __syncthreads();

        const int pl = tid >> 1;            // 0..63
        const int il = pl >> 3;
        const int jl = pl & 7;
        const int rh = tid & 1;             // row-half: rows 4rh..4rh+3

        float acc[8][4];                    // [col s][row rr]
#pragma unroll
        for (int s = 0; s < 8; s++)
#pragma unroll
            for (int rr = 0; rr < 4; rr++) acc[s][rr] = 0.f;

#pragma unroll
        for (int t = 0; t < 8; t++) {
            float av[4], bv[8];
#pragma unroll
            for (int rr = 0; rr < 4; rr++) av[rr] = As[il][t * 8 + 4 * rh + rr];
#pragma unroll
            for (int s = 0; s < 8; s++)   bv[s]  = Bs[jl][t * 8 + s];
#pragma unroll
            for (int s = 0; s < 8; s++) {
                acc[s][0] = fmaf(av[0], bv[s], acc[s][0]);
                acc[s][1] = fmaf(av[1], bv[s], acc[s][1]);
                acc[s][2] = fmaf(av[2], bv[s], acc[s][2]);
                acc[s][3] = fmaf(av[3], bv[s], acc[s][3]);
            }
        }

        const int pair = (itile + il) * 256 + (jtile + jl);
        float4* dst = (float4*)Hm + (size_t)pair * 16 + rh * 8;
#pragma unroll
        for (int s = 0; s < 8; s++)
            dst[s] = make_float4(acc[s][0], acc[s][1], acc[s][2], acc[s][3]);
    } else if (bid < 2560) {
        // H0: thread per pair. o[s] = sum_t G0[i,t] * G1[t,j,s]
        const int pair = (bid - 2048) * 128 + tid;
        const int i = pair >> 8, j = pair & 255;
        float4 b[16];
#pragma unroll
        for (int t = 0; t < 8; t++) {
            const float4* Br = (const float4*)(G1 + (t * 256 + j) * 8);
            b[2 * t]     = __ldg(Br);
            b[2 * t + 1] = __ldg(Br + 1);
        }
        const float4* Ar = (const float4*)(G0 + i * 8);
        float4 a0 = __ldg(Ar), a1 = __ldg(Ar + 1);
        const float a[8] = { a0.x, a0.y, a0.z, a0.w, a1.x, a1.y, a1.z, a1.w };
        float o[8];
#pragma unroll
        for (int s = 0; s < 8; s++) o[s] = 0.f;
#pragma unroll
        for (int t = 0; t < 8; t++) {
            const float w = a[t];
            o[0] = fmaf(w, b[2 * t].x, o[0]);     o[1] = fmaf(w, b[2 * t].y, o[1]);
            o[2] = fmaf(w, b[2 * t].z, o[2]);     o[3] = fmaf(w, b[2 * t].w, o[3]);
            o[4] = fmaf(w, b[2 * t + 1].x, o[4]); o[5] = fmaf(w, b[2 * t + 1].y, o[5]);
            o[6] = fmaf(w, b[2 * t + 1].z, o[6]); o[7] = fmaf(w, b[2 * t + 1].w, o[7]);
        }
        float4* dst = (float4*)(H0v + (size_t)pair * 8);
        dst[0] = make_float4(o[0], o[1], o[2], o[3]);
        dst[1] = make_float4(o[4], o[5], o[6], o[7]);
    } else {
        // H3: thread per pair. o[r] = sum_t G6[r,i,t] * G7[t*256+j]
        const int pair = (bid - 2560) * 128 + tid;
        const int i = pair >> 8, j = pair & 255;
        float b[8];
#pragma unroll
        for (int t = 0; t < 8; t++) b[t] = __ldg(G7 + t * 256 + j);
        float4 av[16];
#pragma unroll
        for (int r = 0; r < 8; r++) {
            const float4* Ar = (const float4*)(G6 + (r * 256 + i) * 8);
            av[2 * r]     = __ldg(Ar);
            av[2 * r + 1] = __ldg(Ar + 1);
        }
        float o[8];
#pragma unroll
        for (int r = 0; r < 8; r++) {
            o[r] = av[2 * r].x * b[0] + av[2 * r].y * b[1]
                 + av[2 * r].z * b[2] + av[2 * r].w * b[3]
                 + av[2 * r + 1].x * b[4] + av[2 * r + 1].y * b[5]
                 + av[2 * r + 1].z * b[6] + av[2 * r + 1].w * b[7];
        }
        float4* dst = (float4*)(H3v + (size_t)pair * 8);
        dst[0] = make_float4(o[0], o[1], o[2], o[3]);
        dst[1] = make_float4(o[4], o[5], o[6], o[7]);
    }
}

// ---------------- Main: 8 lanes per element, column scheme (R15 best) ----------------
__global__ void __launch_bounds__(512)
tt_main(const int* __restrict__ states, const int* __restrict__ actions,
        float* __restrict__ out, int Btot)
{
    const unsigned F = 0xffffffffu;
    const int tid  = threadIdx.x;
    const int gw   = (blockIdx.x * 512 + tid) >> 5;   // global warp: 4 elements
    const int lane = tid & 31;
    const int g    = lane >> 3;                       // element slot in warp
    const int j    = lane & 7;                        // rank lane
    const int gb   = g * 8;                           // group base lane

    // Coalesced index fetch for the warp's 4 elements.
    int raw = 0;
    if (lane < 28) {
        long idx = (long)gw * 28 + lane;
        if (idx < (long)Btot * 7) raw = __ldg(states + idx);
    }
    int act = 0;
    if (lane < 4) {
        int idx = gw * 4 + lane;
        if (idx < Btot) act = __ldg(actions + idx);
    }

    const int s0 = __shfl_sync(F, raw, g * 7 + 0);
    const int s1 = __shfl_sync(F, raw, g * 7 + 1);
    const int s2 = __shfl_sync(F, raw, g * 7 + 2);
    const int s3 = __shfl_sync(F, raw, g * 7 + 3);
    const int s4 = __shfl_sync(F, raw, g * 7 + 4);
    const int s5 = __shfl_sync(F, raw, g * 7 + 5);
    const int s6 = __shfl_sync(F, raw, g * 7 + 6);
    const int aa = __shfl_sync(F, act, g);

    // Table loads (addresses independent of all compute).
    const float4* P1 = (const float4*)H1v + (size_t)(s2 * 256 + s3) * 16;
    const float4* P2 = (const float4*)H2v + (size_t)(s4 * 256 + s5) * 16;
    float  v   = __ldg(H0v + (size_t)(s0 * 256 + s1) * 8 + j);
    float4 lo1 = __ldg(P1 + j);
    float4 hi1 = __ldg(P1 + 8 + j);
    float4 lo2 = __ldg(P2 + j);
    float4 hi2 = __ldg(P2 + 8 + j);
    float  h3  = __ldg(H3v + (size_t)(s6 * 256 + aa) * 8 + j);

    // Stage 1: u_j = sum_r v_r * M23[r][j]   (lane j holds col j)
    {
        float u;
        u = __shfl_sync(F, v, gb + 0) * lo1.x;
        u = fmaf(__shfl_sync(F, v, gb + 1), lo1.y, u);
        u = fmaf(__shfl_sync(F, v, gb + 2), lo1.z, u);
        u = fmaf(__shfl_sync(F, v, gb + 3), lo1.w, u);
        u = fmaf(__shfl_sync(F, v, gb + 4), hi1.x, u);
        u = fmaf(__shfl_sync(F, v, gb + 5), hi1.y, u);
        u = fmaf(__shfl_sync(F, v, gb + 6), hi1.z, u);
        u = fmaf(__shfl_sync(F, v, gb + 7), hi1.w, u);
        v = u;
    }
    // Stage 2: M45
    {
        float u;
        u = __shfl_sync(F, v, gb + 0) * lo2.x;
        u = fmaf(__shfl_sync(F, v, gb + 1), lo2.y, u);
        u = fmaf(__shfl_sync(F, v, gb + 2), lo2.z, u);
        u = fmaf(__shfl_sync(F, v, gb + 3), lo2.w, u);
        u = fmaf(__shfl_sync(F, v, gb + 4), hi2.x, u);
        u = fmaf(__shfl_sync(F, v, gb + 5), hi2.y, u);
        u = fmaf(__shfl_sync(F, v, gb + 6), hi2.z, u);
        u = fmaf(__shfl_sync(F, v, gb + 7), hi2.w, u);
        v = u;
    }
    // Final dot with H3 + butterfly sum within the 8-lane group.
    float q = v * h3;
    q += __shfl_xor_sync(F, q, 1);
    q += __shfl_xor_sync(F, q, 2);
    q += __shfl_xor_sync(F, q, 4);

    const int e = gw * 4 + g;
    if (j == 0 && e < Btot) out[e] = q;
}

extern "C" void kernel_launch(void* const* d_in, const int* in_sizes, int n_in,
                              void* d_out, int out_size)
{
    const float* G0 = (const float*)d_in[0];
    const float* G1 = (const float*)d_in[1];
    const float* G2 = (const float*)d_in[2];
    const float* G3 = (const float*)d_in[3];
    const float* G4 = (const float*)d_in[4];
    const float* G5 = (const float*)d_in[5];
    const float* G6 = (const float*)d_in[6];
    const float* G7 = (const float*)d_in[7];
    const int* states  = (const int*)d_in[8];
    const int* actions = (const int*)d_in[9];
    const int B = in_sizes[9];

    build_all<<<3072, 128>>>(G0, G1, G2, G3, G4, G5, G6, G7);

    // 4 elements per warp, 16 warps per block -> 64 elements per block.
    const int grid = (B + 63) / 64;
    tt_main<<<grid, 512>>>(states, actions, (float*)d_out, B);
}